// round 10
// baseline (speedup 1.0000x reference)
#include <cuda_runtime.h>
#include <cuda_bf16.h>
#include <cstdint>
#include <math.h>

// ---------------------------------------------------------------------------
// Problem constants
#define T_TOK 4096
#define H_DIM 1024
#define I_DIM 2048
#define N_EXP 8
#define K_TOP 2
#define MAXROWS 10240   // 8192 pairs + per-expert padding to 128 => 80 tiles

// GEMM tiling
#define BM 128
#define BN 128
#define BK 32
#define ROWB 80                      // bf16 smem row: 64B data + 16B pad
#define ROW8 48                      // int8 smem row: 32B data + 16B pad (conflict-free)
#define AH_TILE (128 * ROWB)         // 10240
#define A8_PLANE (128 * ROW8)        // 6144
#define OFF_AH 0
#define OFF_BH AH_TILE               // 10240
#define OFF_A8 (2 * AH_TILE)         // 20480
#define OFF_B8 (OFF_A8 + 2 * A8_PLANE) // 32768
#define STAGE_BYTES (OFF_B8 + 2 * A8_PLANE) // 45056
#define SMEM_TOTAL (2 * STAGE_BYTES) // 90112 -> still 2 CTAs/SM
#define NROWT (MAXROWS / BM)         // 80 row tiles

// int8 correction scales (power of 2; phase products equal per GEMM)
// GEMM1: A-hi*2^5 x B-lo*2^19  and  A-lo*2^14 x B-hi*2^10  -> 2^24
// GEMM2: A-hi*2^4 x B-lo*2^19  and  A-lo*2^13 x B-hi*2^10  -> 2^23
#define SA_HI_1 32.f
#define SA_LO_1 16384.f
#define SA_HI_2 16.f
#define SA_LO_2 8192.f
#define SB_LO   524288.f
#define SB_HI   1024.f
#define MERGE_1 5.9604644775390625e-8f   // 2^-24
#define MERGE_2 1.1920928955078125e-7f   // 2^-23

// ---------------------------------------------------------------------------
// Scratch (device globals — allocation-free; referenced ONLY from device code)
__device__ int   d_count[N_EXP];
__device__ int   d_cursor[N_EXP];
__device__ int   d_seg[N_EXP + 1];
__device__ int   d_tok[MAXROWS];
__device__ float d_roww[MAXROWS];
__device__ float d_topw[T_TOK * K_TOP];
__device__ int   d_tope[T_TOK * K_TOP];

__device__ unsigned short d_xhi[(size_t)T_TOK * H_DIM];
__device__ unsigned char  d_x8p[(size_t)T_TOK * H_DIM];   // q8(x_hi * 2^5)
__device__ unsigned char  d_x8q[(size_t)T_TOK * H_DIM];   // q8(x_lo * 2^14)
// W1 = gate/up interleaved at 8-col granularity: [E][4096][1024]
__device__ unsigned short d_W1hi[(size_t)N_EXP * 2 * I_DIM * H_DIM];
__device__ unsigned char  d_W18p[(size_t)N_EXP * 2 * I_DIM * H_DIM];  // q8(W_lo*2^19)
__device__ unsigned char  d_W18q[(size_t)N_EXP * 2 * I_DIM * H_DIM];  // q8(W_hi*2^10)
// Wd transposed: [E][1024][2048]
__device__ unsigned short d_Wdhi[(size_t)N_EXP * H_DIM * I_DIM];
__device__ unsigned char  d_Wd8p[(size_t)N_EXP * H_DIM * I_DIM];
__device__ unsigned char  d_Wd8q[(size_t)N_EXP * H_DIM * I_DIM];
__device__ unsigned short d_midhi[(size_t)MAXROWS * I_DIM];
__device__ unsigned char  d_mid8p[(size_t)MAXROWS * I_DIM];  // q8(mid_hi*2^4)
__device__ unsigned char  d_mid8q[(size_t)MAXROWS * I_DIM];  // q8(mid_lo*2^13)

// ---------------------------------------------------------------------------
// PTX macros (baseline PTX only: compiles for compute_103 target)
#define CP16(dst, src, sz) \
    asm volatile("cp.async.cg.shared.global [%0], [%1], 16, %2;" \
                 :: "r"(dst), "l"(src), "r"(sz) : "memory")
#define CP_COMMIT() asm volatile("cp.async.commit_group;" ::: "memory")
#define CP_WAIT0()  asm volatile("cp.async.wait_group 0;" ::: "memory")

#define LDSM_X4(r, addr) \
    asm volatile("ldmatrix.sync.aligned.m8n8.x4.shared.b16 {%0,%1,%2,%3}, [%4];" \
                 : "=r"((r)[0]), "=r"((r)[1]), "=r"((r)[2]), "=r"((r)[3]) : "r"(addr))

#define MMA_BF16(c, a, b) \
    asm volatile("mma.sync.aligned.m16n8k16.row.col.f32.bf16.bf16.f32 " \
                 "{%0,%1,%2,%3}, {%4,%5,%6,%7}, {%8,%9}, {%0,%1,%2,%3};" \
                 : "+f"((c)[0]), "+f"((c)[1]), "+f"((c)[2]), "+f"((c)[3]) \
                 : "r"((a)[0]), "r"((a)[1]), "r"((a)[2]), "r"((a)[3]), \
                   "r"((b)[0]), "r"((b)[1]))

#define MMA_S8(c, a, b) \
    asm volatile("mma.sync.aligned.m16n8k32.row.col.s32.s8.s8.s32 " \
                 "{%0,%1,%2,%3}, {%4,%5,%6,%7}, {%8,%9}, {%0,%1,%2,%3};" \
                 : "+r"((c)[0]), "+r"((c)[1]), "+r"((c)[2]), "+r"((c)[3]) \
                 : "r"((a)[0]), "r"((a)[1]), "r"((a)[2]), "r"((a)[3]), \
                   "r"((b)[0]), "r"((b)[1]))

// bf16 split / int8 quant helpers
__device__ __forceinline__ unsigned short bfbits(float v) {
    __nv_bfloat16 b = __float2bfloat16_rn(v);
    return *reinterpret_cast<unsigned short*>(&b);
}
__device__ __forceinline__ float bfval(unsigned short u) {
    __nv_bfloat16 b;
    *reinterpret_cast<unsigned short*>(&b) = u;
    return __bfloat162float(b);
}
__device__ __forceinline__ unsigned char q8(float v, float s) {
    float q = rintf(v * s);
    q = fminf(fmaxf(q, -127.f), 127.f);
    return (unsigned char)(signed char)(int)q;
}
__device__ __forceinline__ float silu_mul(float g, float u) {
    return g / (1.f + expf(-g)) * u;
}

// ---------------------------------------------------------------------------
__global__ void init_kernel() {
    int tid = threadIdx.x;
    if (tid < N_EXP) { d_count[tid] = 0; d_cursor[tid] = 0; }
    for (int i = tid; i < MAXROWS; i += blockDim.x) d_tok[i] = -1;
}

__global__ void zero_out_kernel(float* __restrict__ out) {
    size_t i = (size_t)blockIdx.x * 256 + threadIdx.x;
    ((float4*)out)[i] = make_float4(0.f, 0.f, 0.f, 0.f);
}

// fp32 x -> bf16 hi + int8 planes
__global__ void convx_kernel(const float* __restrict__ x) {
    size_t i = (size_t)blockIdx.x * 256 + threadIdx.x;  // float4 index
    float4 v = ((const float4*)x)[i];
    ushort4 h;
    uchar4 p, q;
    h.x = bfbits(v.x); h.y = bfbits(v.y); h.z = bfbits(v.z); h.w = bfbits(v.w);
    float a0 = bfval(h.x), a1 = bfval(h.y), a2 = bfval(h.z), a3 = bfval(h.w);
    p.x = q8(a0, SA_HI_1); p.y = q8(a1, SA_HI_1);
    p.z = q8(a2, SA_HI_1); p.w = q8(a3, SA_HI_1);
    q.x = q8(v.x - a0, SA_LO_1); q.y = q8(v.y - a1, SA_LO_1);
    q.z = q8(v.z - a2, SA_LO_1); q.w = q8(v.w - a3, SA_LO_1);
    ((ushort4*)d_xhi)[i] = h;
    ((uchar4*)d_x8p)[i] = p;
    ((uchar4*)d_x8q)[i] = q;
}

// transpose + split: bf16 hi + int8 lo-plane(P) + int8 hi-plane(Q).
// mode 0: Wg -> W1 (interleaved even groups); 1: Wu -> W1 (odd); 2: Wd.
__global__ void wtrans_kernel(const float* __restrict__ W, int mode) {
    __shared__ float tile[64][33];
    const int Kd = (mode == 2) ? I_DIM : H_DIM;
    const int Nd = (mode == 2) ? H_DIM : I_DIM;
    const int Nb = (mode == 2) ? H_DIM : 2 * I_DIM;
    unsigned short* Thi = (mode == 2) ? d_Wdhi : d_W1hi;
    unsigned char*  Tp  = (mode == 2) ? d_Wd8p : d_W18p;
    unsigned char*  Tq  = (mode == 2) ? d_Wd8q : d_W18q;

    int e = blockIdx.z;
    const float* We = W + (size_t)e * Kd * Nd;
    int nbase = blockIdx.x * 32, kbase = blockIdx.y * 64;
    int tid = threadIdx.x, tx = tid & 31, ty = tid >> 5;
#pragma unroll
    for (int r = 0; r < 64; r += 8)
        tile[r + ty][tx] = We[(size_t)(kbase + r + ty) * Nd + nbase + tx];
    __syncthreads();

    size_t ebase = (size_t)e * Nb * Kd;
#pragma unroll
    for (int task = tid; task < 512; task += 256) {
        int n = task >> 4, qq = task & 15;
        int j = nbase + n;
        int np = (mode == 2) ? j
                 : (((j >> 3) << 4) | (mode == 1 ? 8 : 0) | (j & 7));
        ushort4 h;
        uchar4 pl, qh;
#pragma unroll
        for (int c = 0; c < 4; c++) {
            float v = tile[qq * 4 + c][n];
            unsigned short hb = bfbits(v);
            float hv = bfval(hb);
            ((unsigned short*)&h)[c] = hb;
            ((unsigned char*)&pl)[c] = q8(v - hv, SB_LO);
            ((unsigned char*)&qh)[c] = q8(hv, SB_HI);
        }
        size_t o = ebase + (size_t)np * Kd + kbase + qq * 4;
        *(ushort4*)(Thi + o) = h;
        *(uchar4*)(Tp + o) = pl;
        *(uchar4*)(Tq + o) = qh;
    }
}

// One warp per token: logits, softmax, top-2, expert counting.
__global__ void router_kernel(const float* __restrict__ x,
                              const float* __restrict__ gw,
                              float* __restrict__ out_logits) {
    int warp = threadIdx.x >> 5, lane = threadIdx.x & 31;
    int t = blockIdx.x * 8 + warp;
    if (t >= T_TOK) return;
    const float* xr = x + (size_t)t * H_DIM;
    float acc[N_EXP];
#pragma unroll
    for (int e = 0; e < N_EXP; e++) acc[e] = 0.f;
    for (int i = lane; i < H_DIM; i += 32) {
        float xv = xr[i];
        float4 a = __ldg((const float4*)(gw + (size_t)i * N_EXP));
        float4 b = __ldg((const float4*)(gw + (size_t)i * N_EXP) + 1);
        acc[0] += xv * a.x; acc[1] += xv * a.y; acc[2] += xv * a.z; acc[3] += xv * a.w;
        acc[4] += xv * b.x; acc[5] += xv * b.y; acc[6] += xv * b.z; acc[7] += xv * b.w;
    }
#pragma unroll
    for (int off = 16; off > 0; off >>= 1)
#pragma unroll
        for (int e = 0; e < N_EXP; e++)
            acc[e] += __shfl_xor_sync(0xffffffffu, acc[e], off);
    if (lane == 0) {
#pragma unroll
        for (int e = 0; e < N_EXP; e++) out_logits[(size_t)t * N_EXP + e] = acc[e];
        float m = acc[0];
#pragma unroll
        for (int e = 1; e < N_EXP; e++) m = fmaxf(m, acc[e]);
        float p[N_EXP], s = 0.f;
#pragma unroll
        for (int e = 0; e < N_EXP; e++) { p[e] = expf(acc[e] - m); s += p[e]; }
        float inv = 1.f / s;
        int i0 = 0; float b0 = p[0];
#pragma unroll
        for (int e = 1; e < N_EXP; e++) if (p[e] > b0) { b0 = p[e]; i0 = e; }
        int i1 = -1; float b1 = -1.f;
#pragma unroll
        for (int e = 0; e < N_EXP; e++) if (e != i0 && p[e] > b1) { b1 = p[e]; i1 = e; }
        d_tope[t * 2 + 0] = i0; d_topw[t * 2 + 0] = b0 * inv;
        d_tope[t * 2 + 1] = i1; d_topw[t * 2 + 1] = b1 * inv;
        atomicAdd(&d_count[i0], 1);
        atomicAdd(&d_count[i1], 1);
    }
}

__global__ void scan_kernel() {
    if (threadIdx.x == 0) {
        int off = 0;
#pragma unroll
        for (int e = 0; e < N_EXP; e++) { d_seg[e] = off; off += (d_count[e] + 127) & ~127; }
        d_seg[N_EXP] = off;
    }
}

__global__ void scatter_kernel() {
    int t = blockIdx.x * blockDim.x + threadIdx.x;
    if (t >= T_TOK) return;
#pragma unroll
    for (int k = 0; k < K_TOP; k++) {
        int e = d_tope[t * 2 + k];
        int pos = atomicAdd(&d_cursor[e], 1);
        int row = d_seg[e] + pos;
        d_tok[row] = t;
        d_roww[row] = d_topw[t * 2 + k];
    }
}

// ---------------------------------------------------------------------------
// Grouped GEMM: bf16 hi pass (m16n8k16) + int8 correction pass (m16n8k32 s8,
// exact s32 accumulate, merged with power-of-2 scale into fp32 acc).
// MODE 0: A = gather(x), B = W1 interleaved; epilogue -> mid (hi + int8 planes)
// MODE 1: A = mid, B = Wd; epilogue -> atomicAdd weighted combine into out
template <int MODE>
__global__ __launch_bounds__(256, 2)
void mma_gemm_kernel(float* __restrict__ out)
{
    constexpr int Kdim = (MODE == 0) ? H_DIM : I_DIM;
    constexpr int Nb   = (MODE == 0) ? 2 * I_DIM : H_DIM;
    constexpr int NT   = Nb / BN;
    constexpr int GR   = (MODE == 0) ? 8 : 32;
    const float MERGE  = (MODE == 0) ? MERGE_1 : MERGE_2;

    extern __shared__ char sm[];

    // supertile raster (kept from R9; neutral, harmless)
    int lin = blockIdx.x;
    int group = lin / (GR * NT);
    int rem = lin - group * (GR * NT);
    int rows_here = NROWT - group * GR;
    if (rows_here > GR) rows_here = GR;
    int rt = group * GR + rem % rows_here;
    int nt = rem / rows_here;

    int row0 = rt * BM;
    if (row0 >= d_seg[N_EXP]) return;
    int n0 = nt * BN;

    const unsigned short* __restrict__ Ahi_g = (MODE == 0) ? d_xhi : d_midhi;
    const unsigned char*  __restrict__ A8p_g = (MODE == 0) ? d_x8p : d_mid8p;
    const unsigned char*  __restrict__ A8q_g = (MODE == 0) ? d_x8q : d_mid8q;
    const unsigned short* __restrict__ Bhi_g = (MODE == 0) ? d_W1hi : d_Wdhi;
    const unsigned char*  __restrict__ B8p_g = (MODE == 0) ? d_W18p : d_Wd8p;
    const unsigned char*  __restrict__ B8q_g = (MODE == 0) ? d_W18q : d_Wd8q;

    uint32_t sbase = (uint32_t)__cvta_generic_to_shared(sm);
    int tid = threadIdx.x, lane = tid & 31, wid = tid >> 5;

    int e = 0;
#pragma unroll
    for (int i = 0; i < N_EXP - 1; i++) if (row0 >= d_seg[i + 1]) e = i + 1;

    // ---- bf16 load setup: rows r1, r1+64 at 16B chunk kc (4 chunks/64B row)
    int r1 = tid >> 2, kc = tid & 3;
    const unsigned short *pAh[2], *pBh[2];
    uint32_t szA[2], dstoff[2];
#pragma unroll
    for (int h2 = 0; h2 < 2; h2++) {
        int r = r1 + h2 * 64;
        dstoff[h2] = (uint32_t)(r * ROWB + kc * 16);
        if (MODE == 0) {
            int tok = d_tok[row0 + r];
            pAh[h2] = (tok >= 0) ? Ahi_g + (size_t)tok * Kdim + kc * 8 : Ahi_g;
            szA[h2] = (tok >= 0) ? 16 : 0;
        } else {
            pAh[h2] = Ahi_g + (size_t)(row0 + r) * Kdim + kc * 8;
            szA[h2] = 16;
        }
        pBh[h2] = Bhi_g + ((size_t)e * Nb + n0 + r) * Kdim + kc * 8;
    }

    // ---- int8 load setup: row ra (0..127), chunk kc8 (2 per 32B row)
    int ra = tid >> 1, kc8 = (tid & 1) * 16;
    const unsigned char *pA8p, *pA8q, *pB8p, *pB8q;
    uint32_t sz8, dst8 = (uint32_t)(ra * ROW8 + kc8);
    if (MODE == 0) {
        int tok = d_tok[row0 + ra];
        pA8p = (tok >= 0) ? A8p_g + (size_t)tok * Kdim + kc8 : A8p_g;
        pA8q = (tok >= 0) ? A8q_g + (size_t)tok * Kdim + kc8 : A8q_g;
        sz8 = (tok >= 0) ? 16 : 0;
    } else {
        pA8p = A8p_g + (size_t)(row0 + ra) * Kdim + kc8;
        pA8q = A8q_g + (size_t)(row0 + ra) * Kdim + kc8;
        sz8 = 16;
    }
    size_t bo8 = ((size_t)e * Nb + n0 + ra) * Kdim + kc8;
    pB8p = B8p_g + bo8;
    pB8q = B8q_g + bo8;

#define LOAD_STAGE(s, kof) do { \
    uint32_t sb_ = sbase + (s) * STAGE_BYTES; \
    _Pragma("unroll") \
    for (int h2 = 0; h2 < 2; h2++) { \
        CP16(sb_ + OFF_AH + dstoff[h2], pAh[h2] + (kof), szA[h2]); \
        CP16(sb_ + OFF_BH + dstoff[h2], pBh[h2] + (kof), 16u); \
    } \
    CP16(sb_ + OFF_A8 + dst8,            pA8p + (kof), sz8); \
    CP16(sb_ + OFF_A8 + A8_PLANE + dst8, pA8q + (kof), sz8); \
    CP16(sb_ + OFF_B8 + dst8,            pB8p + (kof), 16u); \
    CP16(sb_ + OFF_B8 + A8_PLANE + dst8, pB8q + (kof), 16u); \
} while (0)

    // ---- compute setup
    int wm = (wid & 1) * 64, wn = (wid >> 1) * 32;
    uint32_t a_off = (uint32_t)((wm + (lane & 15)) * ROWB + (lane >> 4) * 16);
    uint32_t b_off = (uint32_t)((wn + (lane & 7) + ((lane >> 4) << 3)) * ROWB +
                                ((lane >> 3) & 1) * 16);
    // int8 ldmatrix lane addressing (m16n8k32 fragments, rows of 32B data)
    uint32_t a8_off = (uint32_t)((wm + (lane & 7) + ((lane >> 3) & 1) * 8) * ROW8 +
                                 (lane >> 4) * 16);
    uint32_t b8_off = (uint32_t)((wn + (lane & 7) + (lane >> 4) * 8) * ROW8 +
                                 ((lane >> 3) & 1) * 16);

    float acc[4][4][4];
#pragma unroll
    for (int i = 0; i < 4; i++)
#pragma unroll
        for (int j = 0; j < 4; j++)
#pragma unroll
            for (int q = 0; q < 4; q++) acc[i][j][q] = 0.f;

    const int nk = Kdim / BK;
    LOAD_STAGE(0, 0);
    CP_COMMIT();

    for (int ks = 0; ks < nk; ks++) {
        int s = ks & 1;
        CP_WAIT0();
        __syncthreads();

        if (ks + 1 < nk) {
            LOAD_STAGE(s ^ 1, (ks + 1) * BK);
            CP_COMMIT();
        }

        uint32_t sb = sbase + s * STAGE_BYTES;

        // ---- bf16 hi pass (2 x k16)
#pragma unroll
        for (int h = 0; h < 2; h++) {
            uint32_t bh[4][2];
#pragma unroll
            for (int jp = 0; jp < 2; jp++) {
                uint32_t tmp[4];
                LDSM_X4(tmp, sb + OFF_BH + b_off + jp * (16 * ROWB) + h * 32);
                bh[jp * 2][0] = tmp[0]; bh[jp * 2][1] = tmp[1];
                bh[jp * 2 + 1][0] = tmp[2]; bh[jp * 2 + 1][1] = tmp[3];
            }
#pragma unroll
            for (int i = 0; i < 4; i++) {
                uint32_t ah[4];
                LDSM_X4(ah, sb + OFF_AH + a_off + i * (16 * ROWB) + h * 32);
#pragma unroll
                for (int j = 0; j < 4; j++)
                    MMA_BF16(acc[i][j], ah, bh[j]);
            }
        }

        // ---- int8 correction pass (1 x k32, two phases, shared s32 acc)
        {
            uint32_t b8p[4][2], b8q[4][2];
#pragma unroll
            for (int jp = 0; jp < 2; jp++) {
                uint32_t tmp[4];
                LDSM_X4(tmp, sb + OFF_B8 + b8_off + jp * (16 * ROW8));
                b8p[jp * 2][0] = tmp[0]; b8p[jp * 2][1] = tmp[1];
                b8p[jp * 2 + 1][0] = tmp[2]; b8p[jp * 2 + 1][1] = tmp[3];
                LDSM_X4(tmp, sb + OFF_B8 + A8_PLANE + b8_off + jp * (16 * ROW8));
                b8q[jp * 2][0] = tmp[0]; b8q[jp * 2][1] = tmp[1];
                b8q[jp * 2 + 1][0] = tmp[2]; b8q[jp * 2 + 1][1] = tmp[3];
            }
#pragma unroll
            for (int i = 0; i < 4; i++) {
                uint32_t a8p[4], a8q[4];
                LDSM_X4(a8p, sb + OFF_A8 + a8_off + i * (16 * ROW8));
                LDSM_X4(a8q, sb + OFF_A8 + A8_PLANE + a8_off + i * (16 * ROW8));
#pragma unroll
                for (int j = 0; j < 4; j++) {
                    int sacc[4] = {0, 0, 0, 0};
                    MMA_S8(sacc, a8p, b8p[j]);   // hi_A x lo_B
                    MMA_S8(sacc, a8q, b8q[j]);   // lo_A x hi_B
                    acc[i][j][0] += (float)sacc[0] * MERGE;
                    acc[i][j][1] += (float)sacc[1] * MERGE;
                    acc[i][j][2] += (float)sacc[2] * MERGE;
                    acc[i][j][3] += (float)sacc[3] * MERGE;
                }
            }
        }
    }

    // ---- epilogue
    int rin = lane >> 2, cin = (lane & 3) * 2;
    if (MODE == 0) {
        int midcol0 = (n0 + wn) >> 1;
#pragma unroll
        for (int i = 0; i < 4; i++)
#pragma unroll
            for (int jp = 0; jp < 2; jp++) {
                const float* g = acc[i][jp * 2];
                const float* u = acc[i][jp * 2 + 1];
                int colb = midcol0 + jp * 8 + cin;
#pragma unroll
                for (int hf = 0; hf < 2; hf++) {
                    float m0 = silu_mul(g[hf * 2 + 0], u[hf * 2 + 0]);
                    float m1 = silu_mul(g[hf * 2 + 1], u[hf * 2 + 1]);
                    ushort2 h2v;
                    h2v.x = bfbits(m0); h2v.y = bfbits(m1);
                    float h0 = bfval(h2v.x), h1 = bfval(h2v.y);
                    uchar2 p2, q2;
                    p2.x = q8(h0, SA_HI_2);      p2.y = q8(h1, SA_HI_2);
                    q2.x = q8(m0 - h0, SA_LO_2); q2.y = q8(m1 - h1, SA_LO_2);
                    size_t off = (size_t)(row0 + wm + i * 16 + rin + hf * 8) * I_DIM + colb;
                    *(ushort2*)(d_midhi + off) = h2v;
                    *(uchar2*)(d_mid8p + off) = p2;
                    *(uchar2*)(d_mid8q + off) = q2;
                }
            }
    } else {
        int   tokA[4], tokB[4];
        float wA[4], wB[4];
#pragma unroll
        for (int i = 0; i < 4; i++) {
            int rr = row0 + wm + i * 16 + rin;
            tokA[i] = d_tok[rr];     wA[i] = d_roww[rr];
            tokB[i] = d_tok[rr + 8]; wB[i] = d_roww[rr + 8];
        }
#pragma unroll
        for (int i = 0; i < 4; i++)
#pragma unroll
            for (int j = 0; j < 4; j++) {
                int col = n0 + wn + j * 8 + cin;
                if (tokA[i] >= 0) {
                    float* p = out + (size_t)tokA[i] * H_DIM + col;
                    atomicAdd(p,     wA[i] * acc[i][j][0]);
                    atomicAdd(p + 1, wA[i] * acc[i][j][1]);
                }
                if (tokB[i] >= 0) {
                    float* p = out + (size_t)tokB[i] * H_DIM + col;
                    atomicAdd(p,     wB[i] * acc[i][j][2]);
                    atomicAdd(p + 1, wB[i] * acc[i][j][3]);
                }
            }
    }
#undef LOAD_STAGE
}

// ---------------------------------------------------------------------------
extern "C" void kernel_launch(void* const* d_in, const int* in_sizes, int n_in,
                              void* d_out, int out_size) {
    const float* x  = (const float*)d_in[0];  // [4096, 1024]
    const float* gw = (const float*)d_in[1];  // [1024, 8]
    const float* Wg = (const float*)d_in[2];  // [8, 1024, 2048]
    const float* Wu = (const float*)d_in[3];  // [8, 1024, 2048]
    const float* Wd = (const float*)d_in[4];  // [8, 2048, 1024]
    float* out = (float*)d_out;               // final (4194304) then logits (32768)
    float* out_logits = out + (size_t)T_TOK * H_DIM;

    static cudaStream_t s_side = nullptr;
    static cudaEvent_t ev_fork = nullptr, ev_join = nullptr;
    if (!s_side) {
        cudaStreamCreateWithFlags(&s_side, cudaStreamNonBlocking);
        cudaEventCreateWithFlags(&ev_fork, cudaEventDisableTiming);
        cudaEventCreateWithFlags(&ev_join, cudaEventDisableTiming);
        cudaFuncSetAttribute(mma_gemm_kernel<0>, cudaFuncAttributeMaxDynamicSharedMemorySize, SMEM_TOTAL);
        cudaFuncSetAttribute(mma_gemm_kernel<1>, cudaFuncAttributeMaxDynamicSharedMemorySize, SMEM_TOTAL);
    }

    // Fork: weight transposes on a side stream
    cudaEventRecord(ev_fork, 0);
    cudaStreamWaitEvent(s_side, ev_fork, 0);
    wtrans_kernel<<<dim3(I_DIM / 32, H_DIM / 64, N_EXP), 256, 0, s_side>>>(Wg, 0);
    wtrans_kernel<<<dim3(I_DIM / 32, H_DIM / 64, N_EXP), 256, 0, s_side>>>(Wu, 1);
    wtrans_kernel<<<dim3(H_DIM / 32, I_DIM / 64, N_EXP), 256, 0, s_side>>>(Wd, 2);
    cudaEventRecord(ev_join, s_side);

    // Main stream: dispatch chain
    init_kernel<<<1, 256>>>();
    zero_out_kernel<<<(T_TOK * H_DIM / 4) / 256, 256>>>(out);
    convx_kernel<<<(T_TOK * H_DIM / 4) / 256, 256>>>(x);
    router_kernel<<<T_TOK / 8, 256>>>(x, gw, out_logits);
    scan_kernel<<<1, 32>>>();
    scatter_kernel<<<T_TOK / 256, 256>>>();

    cudaStreamWaitEvent(0, ev_join, 0);

    // GEMM1 (fused act) and GEMM2 (fused combine)
    mma_gemm_kernel<0><<<NROWT * ((2 * I_DIM) / BN), 256, SMEM_TOTAL>>>(nullptr);
    mma_gemm_kernel<1><<<NROWT * (H_DIM / BN), 256, SMEM_TOTAL>>>(out);
}

// round 11
// speedup vs baseline: 2.2290x; 2.2290x over previous
#include <cuda_runtime.h>
#include <cuda_bf16.h>
#include <cstdint>
#include <math.h>

// ---------------------------------------------------------------------------
// Problem constants
#define T_TOK 4096
#define H_DIM 1024
#define I_DIM 2048
#define N_EXP 8
#define K_TOP 2
#define MAXROWS 10240   // 8192 pairs + per-expert padding to 128 => 80 tiles

// GEMM tiling
#define BM 128
#define BN 128
#define BK 32
#define ROWB 80                      // padded smem row: 32 bf16 (64B) + 16B pad
#define TILE_BYTES (128 * ROWB)      // 10240
#define STAGE_BYTES (4 * TILE_BYTES) // Ahi, Alo, Bhi, Blo
#define SMEM_TOTAL (2 * STAGE_BYTES) // 81920 -> 2 CTAs/SM
#define NROWT (MAXROWS / BM)         // 80 row tiles

// ---------------------------------------------------------------------------
// Scratch (device globals — allocation-free; referenced ONLY from device code)
// NOTE: zero-initialized at module load; tail_kernel restores that state each
// call so graph replays are deterministic.
__device__ int   d_count[N_EXP];
__device__ int   d_cursor[N_EXP];
__device__ int   d_tok[MAXROWS];
__device__ float d_roww[MAXROWS];
__device__ float d_topw[T_TOK * K_TOP];
__device__ int   d_tope[T_TOK * K_TOP];

__device__ unsigned short d_xhi[(size_t)T_TOK * H_DIM];
__device__ unsigned short d_xlo[(size_t)T_TOK * H_DIM];
// W1 = gate/up interleaved at 8-col granularity: [E][4096][1024]
__device__ unsigned short d_W1hi[(size_t)N_EXP * 2 * I_DIM * H_DIM];
__device__ unsigned short d_W1lo[(size_t)N_EXP * 2 * I_DIM * H_DIM];
// Wd transposed: [E][1024][2048]
__device__ unsigned short d_Wdhi[(size_t)N_EXP * H_DIM * I_DIM];
__device__ unsigned short d_Wdlo[(size_t)N_EXP * H_DIM * I_DIM];
__device__ unsigned short d_midhi[(size_t)MAXROWS * I_DIM];
__device__ unsigned short d_midlo[(size_t)MAXROWS * I_DIM];

// ---------------------------------------------------------------------------
// PTX macros (baseline PTX only: compiles for compute_103 target)
#define CP16(dst, src, sz) \
    asm volatile("cp.async.cg.shared.global [%0], [%1], 16, %2;" \
                 :: "r"(dst), "l"(src), "r"(sz) : "memory")
#define CP_COMMIT() asm volatile("cp.async.commit_group;" ::: "memory")
#define CP_WAIT0()  asm volatile("cp.async.wait_group 0;" ::: "memory")

#define LDSM_X4(r, addr) \
    asm volatile("ldmatrix.sync.aligned.m8n8.x4.shared.b16 {%0,%1,%2,%3}, [%4];" \
                 : "=r"((r)[0]), "=r"((r)[1]), "=r"((r)[2]), "=r"((r)[3]) : "r"(addr))

#define MMA_BF16(c, a, b) \
    asm volatile("mma.sync.aligned.m16n8k16.row.col.f32.bf16.bf16.f32 " \
                 "{%0,%1,%2,%3}, {%4,%5,%6,%7}, {%8,%9}, {%0,%1,%2,%3};" \
                 : "+f"((c)[0]), "+f"((c)[1]), "+f"((c)[2]), "+f"((c)[3]) \
                 : "r"((a)[0]), "r"((a)[1]), "r"((a)[2]), "r"((a)[3]), \
                   "r"((b)[0]), "r"((b)[1]))

// bf16 split helpers
__device__ __forceinline__ unsigned short bfbits(float v) {
    __nv_bfloat16 b = __float2bfloat16_rn(v);
    return *reinterpret_cast<unsigned short*>(&b);
}
__device__ __forceinline__ float bfval(unsigned short u) {
    __nv_bfloat16 b;
    *reinterpret_cast<unsigned short*>(&b) = u;
    return __bfloat162float(b);
}
__device__ __forceinline__ void split2(float v, unsigned short& h, unsigned short& l) {
    h = bfbits(v);
    l = bfbits(v - bfval(h));
}
__device__ __forceinline__ float silu_mul(float g, float u) {
    return g / (1.f + expf(-g)) * u;
}

// ---------------------------------------------------------------------------
// Fused pre-kernel: blocks [0,4096) zero the output, [4096,8192) convert x,
// [8192,8704) run the router (one warp per token).
__global__ void pre_kernel(const float* __restrict__ x,
                           const float* __restrict__ gw,
                           float* __restrict__ out,
                           float* __restrict__ out_logits) {
    int b = blockIdx.x;
    if (b < 4096) {
        size_t i = (size_t)b * 256 + threadIdx.x;
        ((float4*)out)[i] = make_float4(0.f, 0.f, 0.f, 0.f);
    } else if (b < 8192) {
        size_t i = (size_t)(b - 4096) * 256 + threadIdx.x;
        float4 v = ((const float4*)x)[i];
        ushort4 h, l;
        split2(v.x, h.x, l.x); split2(v.y, h.y, l.y);
        split2(v.z, h.z, l.z); split2(v.w, h.w, l.w);
        ((ushort4*)d_xhi)[i] = h;
        ((ushort4*)d_xlo)[i] = l;
    } else {
        int warp = threadIdx.x >> 5, lane = threadIdx.x & 31;
        int t = (b - 8192) * 8 + warp;
        if (t >= T_TOK) return;
        const float* xr = x + (size_t)t * H_DIM;
        float acc[N_EXP];
#pragma unroll
        for (int e = 0; e < N_EXP; e++) acc[e] = 0.f;
        for (int i = lane; i < H_DIM; i += 32) {
            float xv = xr[i];
            float4 a = __ldg((const float4*)(gw + (size_t)i * N_EXP));
            float4 bb = __ldg((const float4*)(gw + (size_t)i * N_EXP) + 1);
            acc[0] += xv * a.x; acc[1] += xv * a.y; acc[2] += xv * a.z; acc[3] += xv * a.w;
            acc[4] += xv * bb.x; acc[5] += xv * bb.y; acc[6] += xv * bb.z; acc[7] += xv * bb.w;
        }
#pragma unroll
        for (int off = 16; off > 0; off >>= 1)
#pragma unroll
            for (int e = 0; e < N_EXP; e++)
                acc[e] += __shfl_xor_sync(0xffffffffu, acc[e], off);
        if (lane == 0) {
#pragma unroll
            for (int e = 0; e < N_EXP; e++) out_logits[(size_t)t * N_EXP + e] = acc[e];
            float m = acc[0];
#pragma unroll
            for (int e = 1; e < N_EXP; e++) m = fmaxf(m, acc[e]);
            float p[N_EXP], s = 0.f;
#pragma unroll
            for (int e = 0; e < N_EXP; e++) { p[e] = expf(acc[e] - m); s += p[e]; }
            float inv = 1.f / s;
            int i0 = 0; float b0 = p[0];
#pragma unroll
            for (int e = 1; e < N_EXP; e++) if (p[e] > b0) { b0 = p[e]; i0 = e; }
            int i1 = -1; float b1 = -1.f;
#pragma unroll
            for (int e = 0; e < N_EXP; e++) if (e != i0 && p[e] > b1) { b1 = p[e]; i1 = e; }
            d_tope[t * 2 + 0] = i0; d_topw[t * 2 + 0] = b0 * inv;
            d_tope[t * 2 + 1] = i1; d_topw[t * 2 + 1] = b1 * inv;
            atomicAdd(&d_count[i0], 1);
            atomicAdd(&d_count[i1], 1);
        }
    }
}

// transpose + hi/lo split with vectorized writes.
// mode 0: Wg -> W1 (interleaved even groups); 1: Wu -> W1 (odd); 2: Wd.
__global__ void wtrans_kernel(const float* __restrict__ W, int mode) {
    __shared__ float tile[64][33];
    const int Kd = (mode == 2) ? I_DIM : H_DIM;
    const int Nd = (mode == 2) ? H_DIM : I_DIM;
    const int Nb = (mode == 2) ? H_DIM : 2 * I_DIM;
    unsigned short* Thi = (mode == 2) ? d_Wdhi : d_W1hi;
    unsigned short* Tlo = (mode == 2) ? d_Wdlo : d_W1lo;

    int e = blockIdx.z;
    const float* We = W + (size_t)e * Kd * Nd;
    int nbase = blockIdx.x * 32, kbase = blockIdx.y * 64;
    int tid = threadIdx.x, tx = tid & 31, ty = tid >> 5;
#pragma unroll
    for (int r = 0; r < 64; r += 8)
        tile[r + ty][tx] = We[(size_t)(kbase + r + ty) * Nd + nbase + tx];
    __syncthreads();

    size_t ebase = (size_t)e * Nb * Kd;
#pragma unroll
    for (int task = tid; task < 512; task += 256) {
        int n = task >> 4, q = task & 15;
        int j = nbase + n;
        int np = (mode == 2) ? j
                 : (((j >> 3) << 4) | (mode == 1 ? 8 : 0) | (j & 7));
        ushort4 h, l;
        split2(tile[q * 4 + 0][n], h.x, l.x);
        split2(tile[q * 4 + 1][n], h.y, l.y);
        split2(tile[q * 4 + 2][n], h.z, l.z);
        split2(tile[q * 4 + 3][n], h.w, l.w);
        size_t o = ebase + (size_t)np * Kd + kbase + q * 4;
        *(ushort4*)(Thi + o) = h;
        *(ushort4*)(Tlo + o) = l;
    }
}

// Scatter (blocks 0..15) + padding-sentinel fill (block 16).
// Segment offsets derived per-thread from d_count (no scan kernel).
__global__ void scatter_kernel() {
    int segs[N_EXP];
    {
        int off = 0;
#pragma unroll
        for (int i = 0; i < N_EXP; i++) { segs[i] = off; off += (d_count[i] + 127) & ~127; }
    }
    int b = blockIdx.x;
    if (b < 16) {
        int t = b * 256 + threadIdx.x;
#pragma unroll
        for (int k = 0; k < K_TOP; k++) {
            int e = d_tope[t * 2 + k];
            int pos = atomicAdd(&d_cursor[e], 1);
            int row = segs[e] + pos;
            d_tok[row] = t;
            d_roww[row] = d_topw[t * 2 + k];
        }
    } else {
        // padding rows get tok = -1 (disjoint from scattered rows)
#pragma unroll
        for (int e = 0; e < N_EXP; e++) {
            int cnt = d_count[e];
            int pad = (cnt + 127) & ~127;
            for (int r = cnt + threadIdx.x; r < pad; r += 256)
                d_tok[segs[e] + r] = -1;
        }
    }
}

// Reset count/cursor for the next graph replay (runs after GEMM2).
__global__ void tail_kernel() {
    int tid = threadIdx.x;
    if (tid < N_EXP) { d_count[tid] = 0; d_cursor[tid] = 0; }
}

// ---------------------------------------------------------------------------
// Grouped GEMM on mma.sync.m16n8k16 bf16, hi/lo split (3 passes), fp32 acc.
// MODE 0: A = gather(x) [K=1024], B = W1 (g/u interleaved), epilogue fuses
//         silu(g)*u -> bf16 hi/lo -> d_mid  (acc j even = gate, odd = up)
// MODE 1: A = mid [K=2048], B = Wd, epilogue fuses weighted combine:
//         out[token] += w_row * acc  (atomicAdd; 2 adds/element -> deterministic)
// 128x128x32 CTA tile, 8 warps of 64x32, 2-stage cp.async, 2 CTAs/SM,
// single __syncthreads per K-step (prefetch issued after the barrier).
template <int MODE>
__global__ __launch_bounds__(256, 2)
void mma_gemm_kernel(float* __restrict__ out)
{
    constexpr int Kdim = (MODE == 0) ? H_DIM : I_DIM;
    constexpr int Nb   = (MODE == 0) ? 2 * I_DIM : H_DIM;

    extern __shared__ char sm[];
    int row0 = blockIdx.x * BM;

    // segment lookup from counts (no d_seg array)
    int e = 0;
    {
        int off = 0;
#pragma unroll
        for (int i = 0; i < N_EXP; i++) {
            if (row0 >= off) e = i;
            off += (d_count[i] + 127) & ~127;
        }
        if (row0 >= off) return;
    }

    const unsigned short* __restrict__ Ahi_g = (MODE == 0) ? d_xhi : d_midhi;
    const unsigned short* __restrict__ Alo_g = (MODE == 0) ? d_xlo : d_midlo;
    const unsigned short* __restrict__ Bhi_g = (MODE == 0) ? d_W1hi : d_Wdhi;
    const unsigned short* __restrict__ Blo_g = (MODE == 0) ? d_W1lo : d_Wdlo;

    uint32_t sbase = (uint32_t)__cvta_generic_to_shared(sm);
    int tid = threadIdx.x, lane = tid & 31, wid = tid >> 5;
    int n0 = blockIdx.y * BN;

    // ---- per-thread load setup: 2 rows per tile (r and r+64), 16B chunk kc
    int r1 = tid >> 2, kc = tid & 3;
    const unsigned short *pAh[2], *pAl[2], *pBh[2], *pBl[2];
    uint32_t szA[2], dstoff[2];
#pragma unroll
    for (int h2 = 0; h2 < 2; h2++) {
        int r = r1 + h2 * 64;
        dstoff[h2] = (uint32_t)(r * ROWB + kc * 16);
        if (MODE == 0) {
            int tok = d_tok[row0 + r];
            if (tok >= 0) {
                pAh[h2] = Ahi_g + (size_t)tok * Kdim + kc * 8;
                pAl[h2] = Alo_g + (size_t)tok * Kdim + kc * 8;
                szA[h2] = 16;
            } else {
                pAh[h2] = Ahi_g; pAl[h2] = Alo_g; szA[h2] = 0;  // zero-fill
            }
        } else {
            pAh[h2] = Ahi_g + (size_t)(row0 + r) * Kdim + kc * 8;
            pAl[h2] = Alo_g + (size_t)(row0 + r) * Kdim + kc * 8;
            szA[h2] = 16;
        }
        size_t bo = ((size_t)e * Nb + n0 + r) * Kdim + kc * 8;
        pBh[h2] = Bhi_g + bo;
        pBl[h2] = Blo_g + bo;
    }

#define LOAD_STAGE(s, kof) do { \
    uint32_t sb_ = sbase + (s) * STAGE_BYTES; \
    _Pragma("unroll") \
    for (int h2 = 0; h2 < 2; h2++) { \
        CP16(sb_ + 0 * TILE_BYTES + dstoff[h2], pAh[h2] + (kof), szA[h2]); \
        CP16(sb_ + 1 * TILE_BYTES + dstoff[h2], pAl[h2] + (kof), szA[h2]); \
        CP16(sb_ + 2 * TILE_BYTES + dstoff[h2], pBh[h2] + (kof), 16u); \
        CP16(sb_ + 3 * TILE_BYTES + dstoff[h2], pBl[h2] + (kof), 16u); \
    } \
} while (0)

    // ---- compute setup
    int wm = (wid & 1) * 64, wn = (wid >> 1) * 32;
    uint32_t a_off = (uint32_t)((wm + (lane & 15)) * ROWB + (lane >> 4) * 16);
    uint32_t b_off = (uint32_t)((wn + (lane & 7) + ((lane >> 4) << 3)) * ROWB +
                                ((lane >> 3) & 1) * 16);

    float acc[4][4][4];
#pragma unroll
    for (int i = 0; i < 4; i++)
#pragma unroll
        for (int j = 0; j < 4; j++)
#pragma unroll
            for (int q = 0; q < 4; q++) acc[i][j][q] = 0.f;

    const int nk = Kdim / BK;
    LOAD_STAGE(0, 0);
    CP_COMMIT();

    for (int ks = 0; ks < nk; ks++) {
        int s = ks & 1;
        CP_WAIT0();          // only stage ks's group can be pending
        __syncthreads();     // everyone done computing stage s^1 (prev iter)

        if (ks + 1 < nk) {
            LOAD_STAGE(s ^ 1, (ks + 1) * BK);  // safe: issued after barrier
            CP_COMMIT();
        }

        uint32_t sb = sbase + s * STAGE_BYTES;
#pragma unroll
        for (int h = 0; h < 2; h++) {  // two k16 steps per BK=32
            uint32_t bh[4][2], bl[4][2];
#pragma unroll
            for (int jp = 0; jp < 2; jp++) {
                uint32_t tmp[4];
                uint32_t bd = sb + 2 * TILE_BYTES + b_off + jp * (16 * ROWB) + h * 32;
                LDSM_X4(tmp, bd);
                bh[jp * 2][0] = tmp[0]; bh[jp * 2][1] = tmp[1];
                bh[jp * 2 + 1][0] = tmp[2]; bh[jp * 2 + 1][1] = tmp[3];
                LDSM_X4(tmp, bd + TILE_BYTES);
                bl[jp * 2][0] = tmp[0]; bl[jp * 2][1] = tmp[1];
                bl[jp * 2 + 1][0] = tmp[2]; bl[jp * 2 + 1][1] = tmp[3];
            }
#pragma unroll
            for (int i = 0; i < 4; i++) {
                uint32_t ah[4], al[4];
                uint32_t ad = sb + a_off + i * (16 * ROWB) + h * 32;
                LDSM_X4(ah, ad);
                LDSM_X4(al, ad + TILE_BYTES);
#pragma unroll
                for (int j = 0; j < 4; j++) {
                    MMA_BF16(acc[i][j], ah, bh[j]);
                    MMA_BF16(acc[i][j], ah, bl[j]);
                    MMA_BF16(acc[i][j], al, bh[j]);
                }
            }
        }
    }

    // ---- epilogue
    int rin = lane >> 2, cin = (lane & 3) * 2;
    if (MODE == 0) {
        // acc[i][jp*2] = gate, acc[i][jp*2+1] = up for the SAME logical cols
        int midcol0 = (n0 + wn) >> 1;  // logical mid col base for this warp
#pragma unroll
        for (int i = 0; i < 4; i++)
#pragma unroll
            for (int jp = 0; jp < 2; jp++) {
                const float* g = acc[i][jp * 2];
                const float* u = acc[i][jp * 2 + 1];
                int colb = midcol0 + jp * 8 + cin;
#pragma unroll
                for (int hf = 0; hf < 2; hf++) {
                    float m0 = silu_mul(g[hf * 2 + 0], u[hf * 2 + 0]);
                    float m1 = silu_mul(g[hf * 2 + 1], u[hf * 2 + 1]);
                    ushort2 h2v, l2v;
                    split2(m0, h2v.x, l2v.x);
                    split2(m1, h2v.y, l2v.y);
                    size_t off = (size_t)(row0 + wm + i * 16 + rin + hf * 8) * I_DIM + colb;
                    *(ushort2*)(d_midhi + off) = h2v;
                    *(ushort2*)(d_midlo + off) = l2v;
                }
            }
    } else {
        // fused combine: out[token] += w_row * acc  (2 adds/element total)
        int   tokA[4], tokB[4];
        float wA[4], wB[4];
#pragma unroll
        for (int i = 0; i < 4; i++) {
            int rr = row0 + wm + i * 16 + rin;
            tokA[i] = d_tok[rr];     wA[i] = d_roww[rr];
            tokB[i] = d_tok[rr + 8]; wB[i] = d_roww[rr + 8];
        }
#pragma unroll
        for (int i = 0; i < 4; i++)
#pragma unroll
            for (int j = 0; j < 4; j++) {
                int col = n0 + wn + j * 8 + cin;
                if (tokA[i] >= 0) {
                    float* p = out + (size_t)tokA[i] * H_DIM + col;
                    atomicAdd(p,     wA[i] * acc[i][j][0]);
                    atomicAdd(p + 1, wA[i] * acc[i][j][1]);
                }
                if (tokB[i] >= 0) {
                    float* p = out + (size_t)tokB[i] * H_DIM + col;
                    atomicAdd(p,     wB[i] * acc[i][j][2]);
                    atomicAdd(p + 1, wB[i] * acc[i][j][3]);
                }
            }
    }
#undef LOAD_STAGE
}

// ---------------------------------------------------------------------------
extern "C" void kernel_launch(void* const* d_in, const int* in_sizes, int n_in,
                              void* d_out, int out_size) {
    const float* x  = (const float*)d_in[0];  // [4096, 1024]
    const float* gw = (const float*)d_in[1];  // [1024, 8]
    const float* Wg = (const float*)d_in[2];  // [8, 1024, 2048]
    const float* Wu = (const float*)d_in[3];  // [8, 1024, 2048]
    const float* Wd = (const float*)d_in[4];  // [8, 2048, 1024]
    float* out = (float*)d_out;               // final (4194304) then logits (32768)
    float* out_logits = out + (size_t)T_TOK * H_DIM;

    static cudaStream_t s_side = nullptr;
    static cudaEvent_t ev_fork = nullptr, ev_join = nullptr;
    if (!s_side) {
        cudaStreamCreateWithFlags(&s_side, cudaStreamNonBlocking);
        cudaEventCreateWithFlags(&ev_fork, cudaEventDisableTiming);
        cudaEventCreateWithFlags(&ev_join, cudaEventDisableTiming);
        cudaFuncSetAttribute(mma_gemm_kernel<0>, cudaFuncAttributeMaxDynamicSharedMemorySize, SMEM_TOTAL);
        cudaFuncSetAttribute(mma_gemm_kernel<1>, cudaFuncAttributeMaxDynamicSharedMemorySize, SMEM_TOTAL);
    }

    // Launch order (for ncu -s 5 -c 1): 0-2 wtrans, 3 pre, 4 scatter, 5 GEMM1.
    cudaEventRecord(ev_fork, 0);
    cudaStreamWaitEvent(s_side, ev_fork, 0);
    wtrans_kernel<<<dim3(I_DIM / 32, H_DIM / 64, N_EXP), 256, 0, s_side>>>(Wg, 0);
    wtrans_kernel<<<dim3(I_DIM / 32, H_DIM / 64, N_EXP), 256, 0, s_side>>>(Wu, 1);
    wtrans_kernel<<<dim3(H_DIM / 32, I_DIM / 64, N_EXP), 256, 0, s_side>>>(Wd, 2);
    cudaEventRecord(ev_join, s_side);

    // Main stream: fused zero+convx+router, then scatter (with inline scan)
    pre_kernel<<<8704, 256>>>(x, gw, out, out_logits);
    scatter_kernel<<<17, 256>>>();

    cudaStreamWaitEvent(0, ev_join, 0);

    // GEMM1 (fused act) and GEMM2 (fused combine)
    mma_gemm_kernel<0><<<dim3(NROWT, (2 * I_DIM) / BN), 256, SMEM_TOTAL>>>(nullptr);
    mma_gemm_kernel<1><<<dim3(NROWT, H_DIM / BN), 256, SMEM_TOTAL>>>(out);

    // Reset dispatch state for the next (graph-replayed) call
    tail_kernel<<<1, 32>>>();
}

// round 12
// speedup vs baseline: 5.2150x; 2.3397x over previous
#include <cuda_runtime.h>
#include <cuda_fp16.h>
#include <cstdint>
#include <math.h>

// ---------------------------------------------------------------------------
// Problem constants
#define T_TOK 4096
#define H_DIM 1024
#define I_DIM 2048
#define N_EXP 8
#define K_TOP 2
#define MAXROWS 10240   // 8192 pairs + per-expert padding to 128 => 80 tiles

// GEMM tiling
#define BM 128
#define BN 128
#define BK 32
#define ROWB 80                      // padded smem row: 32 fp16 (64B) + 16B pad
#define TILE_BYTES (128 * ROWB)      // 10240
#define STAGE_BYTES (2 * TILE_BYTES) // A, B (single fp16 planes)
#define SMEM_TOTAL (2 * STAGE_BYTES) // 40960 -> 2 CTAs/SM (reg-limited)
#define NROWT (MAXROWS / BM)         // 80 row tiles

// ---------------------------------------------------------------------------
// Scratch (device globals — allocation-free; referenced ONLY from device code)
// Zero-initialized at module load; tail_kernel restores that state each call.
__device__ int   d_count[N_EXP];
__device__ int   d_cursor[N_EXP];
__device__ int   d_tok[MAXROWS];
__device__ float d_roww[MAXROWS];
__device__ float d_topw[T_TOK * K_TOP];
__device__ int   d_tope[T_TOK * K_TOP];

__device__ unsigned short d_xh[(size_t)T_TOK * H_DIM];            // fp16(x)
// W1 = gate/up interleaved at 8-col granularity: [E][4096][1024] fp16
//   gate col j -> n' = (j>>3)*16 + (j&7);  up col j -> n' = (j>>3)*16 + 8 + (j&7)
__device__ unsigned short d_W1h[(size_t)N_EXP * 2 * I_DIM * H_DIM];
// Wd transposed: [E][1024][2048] fp16
__device__ unsigned short d_Wdh[(size_t)N_EXP * H_DIM * I_DIM];
__device__ unsigned short d_midh[(size_t)MAXROWS * I_DIM];        // fp16(mid)

// ---------------------------------------------------------------------------
// PTX macros (baseline PTX only: compiles for compute_103 target)
#define CP16(dst, src, sz) \
    asm volatile("cp.async.cg.shared.global [%0], [%1], 16, %2;" \
                 :: "r"(dst), "l"(src), "r"(sz) : "memory")
#define CP_COMMIT() asm volatile("cp.async.commit_group;" ::: "memory")
#define CP_WAIT0()  asm volatile("cp.async.wait_group 0;" ::: "memory")

#define LDSM_X4(r, addr) \
    asm volatile("ldmatrix.sync.aligned.m8n8.x4.shared.b16 {%0,%1,%2,%3}, [%4];" \
                 : "=r"((r)[0]), "=r"((r)[1]), "=r"((r)[2]), "=r"((r)[3]) : "r"(addr))

#define MMA_F16(c, a, b) \
    asm volatile("mma.sync.aligned.m16n8k16.row.col.f32.f16.f16.f32 " \
                 "{%0,%1,%2,%3}, {%4,%5,%6,%7}, {%8,%9}, {%0,%1,%2,%3};" \
                 : "+f"((c)[0]), "+f"((c)[1]), "+f"((c)[2]), "+f"((c)[3]) \
                 : "r"((a)[0]), "r"((a)[1]), "r"((a)[2]), "r"((a)[3]), \
                   "r"((b)[0]), "r"((b)[1]))

// fp16 helpers
__device__ __forceinline__ unsigned short h16(float v) {
    __half h = __float2half_rn(v);
    return *reinterpret_cast<unsigned short*>(&h);
}
__device__ __forceinline__ float silu_mul(float g, float u) {
    return g / (1.f + expf(-g)) * u;
}

// ---------------------------------------------------------------------------
// Fused pre-kernel: blocks [0,4096) zero the output, [4096,8192) convert x,
// [8192,8704) run the router (one warp per token).
__global__ void pre_kernel(const float* __restrict__ x,
                           const float* __restrict__ gw,
                           float* __restrict__ out,
                           float* __restrict__ out_logits) {
    int b = blockIdx.x;
    if (b < 4096) {
        size_t i = (size_t)b * 256 + threadIdx.x;
        ((float4*)out)[i] = make_float4(0.f, 0.f, 0.f, 0.f);
    } else if (b < 8192) {
        size_t i = (size_t)(b - 4096) * 256 + threadIdx.x;
        float4 v = ((const float4*)x)[i];
        ushort4 h;
        h.x = h16(v.x); h.y = h16(v.y); h.z = h16(v.z); h.w = h16(v.w);
        ((ushort4*)d_xh)[i] = h;
    } else {
        int warp = threadIdx.x >> 5, lane = threadIdx.x & 31;
        int t = (b - 8192) * 8 + warp;
        if (t >= T_TOK) return;
        const float* xr = x + (size_t)t * H_DIM;
        float acc[N_EXP];
#pragma unroll
        for (int e = 0; e < N_EXP; e++) acc[e] = 0.f;
        for (int i = lane; i < H_DIM; i += 32) {
            float xv = xr[i];
            float4 a = __ldg((const float4*)(gw + (size_t)i * N_EXP));
            float4 bb = __ldg((const float4*)(gw + (size_t)i * N_EXP) + 1);
            acc[0] += xv * a.x; acc[1] += xv * a.y; acc[2] += xv * a.z; acc[3] += xv * a.w;
            acc[4] += xv * bb.x; acc[5] += xv * bb.y; acc[6] += xv * bb.z; acc[7] += xv * bb.w;
        }
#pragma unroll
        for (int off = 16; off > 0; off >>= 1)
#pragma unroll
            for (int e = 0; e < N_EXP; e++)
                acc[e] += __shfl_xor_sync(0xffffffffu, acc[e], off);
        if (lane == 0) {
#pragma unroll
            for (int e = 0; e < N_EXP; e++) out_logits[(size_t)t * N_EXP + e] = acc[e];
            float m = acc[0];
#pragma unroll
            for (int e = 1; e < N_EXP; e++) m = fmaxf(m, acc[e]);
            float p[N_EXP], s = 0.f;
#pragma unroll
            for (int e = 0; e < N_EXP; e++) { p[e] = expf(acc[e] - m); s += p[e]; }
            float inv = 1.f / s;
            int i0 = 0; float b0 = p[0];
#pragma unroll
            for (int e = 1; e < N_EXP; e++) if (p[e] > b0) { b0 = p[e]; i0 = e; }
            int i1 = -1; float b1 = -1.f;
#pragma unroll
            for (int e = 0; e < N_EXP; e++) if (e != i0 && p[e] > b1) { b1 = p[e]; i1 = e; }
            d_tope[t * 2 + 0] = i0; d_topw[t * 2 + 0] = b0 * inv;
            d_tope[t * 2 + 1] = i1; d_topw[t * 2 + 1] = b1 * inv;
            atomicAdd(&d_count[i0], 1);
            atomicAdd(&d_count[i1], 1);
        }
    }
}

// transpose + fp16 convert with vectorized writes.
// mode 0: Wg -> W1 (interleaved even groups); 1: Wu -> W1 (odd); 2: Wd.
__global__ void wtrans_kernel(const float* __restrict__ W, int mode) {
    __shared__ float tile[64][33];
    const int Kd = (mode == 2) ? I_DIM : H_DIM;
    const int Nd = (mode == 2) ? H_DIM : I_DIM;
    const int Nb = (mode == 2) ? H_DIM : 2 * I_DIM;
    unsigned short* Th = (mode == 2) ? d_Wdh : d_W1h;

    int e = blockIdx.z;
    const float* We = W + (size_t)e * Kd * Nd;
    int nbase = blockIdx.x * 32, kbase = blockIdx.y * 64;
    int tid = threadIdx.x, tx = tid & 31, ty = tid >> 5;
#pragma unroll
    for (int r = 0; r < 64; r += 8)
        tile[r + ty][tx] = We[(size_t)(kbase + r + ty) * Nd + nbase + tx];
    __syncthreads();

    size_t ebase = (size_t)e * Nb * Kd;
#pragma unroll
    for (int task = tid; task < 512; task += 256) {
        int n = task >> 4, q = task & 15;
        int j = nbase + n;
        int np = (mode == 2) ? j
                 : (((j >> 3) << 4) | (mode == 1 ? 8 : 0) | (j & 7));
        ushort4 h;
        h.x = h16(tile[q * 4 + 0][n]);
        h.y = h16(tile[q * 4 + 1][n]);
        h.z = h16(tile[q * 4 + 2][n]);
        h.w = h16(tile[q * 4 + 3][n]);
        size_t o = ebase + (size_t)np * Kd + kbase + q * 4;
        *(ushort4*)(Th + o) = h;
    }
}

// Scatter (blocks 0..15) + padding-sentinel fill (block 16).
__global__ void scatter_kernel() {
    int segs[N_EXP];
    {
        int off = 0;
#pragma unroll
        for (int i = 0; i < N_EXP; i++) { segs[i] = off; off += (d_count[i] + 127) & ~127; }
    }
    int b = blockIdx.x;
    if (b < 16) {
        int t = b * 256 + threadIdx.x;
#pragma unroll
        for (int k = 0; k < K_TOP; k++) {
            int e = d_tope[t * 2 + k];
            int pos = atomicAdd(&d_cursor[e], 1);
            int row = segs[e] + pos;
            d_tok[row] = t;
            d_roww[row] = d_topw[t * 2 + k];
        }
    } else {
#pragma unroll
        for (int e = 0; e < N_EXP; e++) {
            int cnt = d_count[e];
            int pad = (cnt + 127) & ~127;
            for (int r = cnt + threadIdx.x; r < pad; r += 256)
                d_tok[segs[e] + r] = -1;
        }
    }
}

// Reset count/cursor for the next graph replay (runs after GEMM2).
__global__ void tail_kernel() {
    int tid = threadIdx.x;
    if (tid < N_EXP) { d_count[tid] = 0; d_cursor[tid] = 0; }
}

// ---------------------------------------------------------------------------
// Grouped GEMM on mma.sync.m16n8k16 fp16 (single pass), fp32 acc.
// MODE 0: A = gather(x) [K=1024], B = W1 (g/u interleaved), epilogue fuses
//         silu(g)*u -> fp16 -> d_midh  (acc j even = gate, odd = up)
// MODE 1: A = mid [K=2048], B = Wd, epilogue fuses weighted combine:
//         out[token] += w_row * acc  (atomicAdd; 2 adds/element -> deterministic)
// 128x128x32 CTA tile, 8 warps of 64x32, 2-stage cp.async, 2 CTAs/SM,
// single __syncthreads per K-step (prefetch issued after the barrier).
template <int MODE>
__global__ __launch_bounds__(256, 2)
void mma_gemm_kernel(float* __restrict__ out)
{
    constexpr int Kdim = (MODE == 0) ? H_DIM : I_DIM;
    constexpr int Nb   = (MODE == 0) ? 2 * I_DIM : H_DIM;

    extern __shared__ char sm[];
    int row0 = blockIdx.x * BM;

    // segment lookup from counts
    int e = 0;
    {
        int off = 0;
#pragma unroll
        for (int i = 0; i < N_EXP; i++) {
            if (row0 >= off) e = i;
            off += (d_count[i] + 127) & ~127;
        }
        if (row0 >= off) return;
    }

    const unsigned short* __restrict__ A_g = (MODE == 0) ? d_xh : d_midh;
    const unsigned short* __restrict__ B_g = (MODE == 0) ? d_W1h : d_Wdh;

    uint32_t sbase = (uint32_t)__cvta_generic_to_shared(sm);
    int tid = threadIdx.x, lane = tid & 31, wid = tid >> 5;
    int n0 = blockIdx.y * BN;

    // ---- per-thread load setup: 2 rows per tile (r and r+64), 16B chunk kc
    int r1 = tid >> 2, kc = tid & 3;
    const unsigned short *pA[2], *pB[2];
    uint32_t szA[2], dstoff[2];
#pragma unroll
    for (int h2 = 0; h2 < 2; h2++) {
        int r = r1 + h2 * 64;
        dstoff[h2] = (uint32_t)(r * ROWB + kc * 16);
        if (MODE == 0) {
            int tok = d_tok[row0 + r];
            pA[h2] = (tok >= 0) ? A_g + (size_t)tok * Kdim + kc * 8 : A_g;
            szA[h2] = (tok >= 0) ? 16 : 0;
        } else {
            pA[h2] = A_g + (size_t)(row0 + r) * Kdim + kc * 8;
            szA[h2] = 16;
        }
        pB[h2] = B_g + ((size_t)e * Nb + n0 + r) * Kdim + kc * 8;
    }

#define LOAD_STAGE(s, kof) do { \
    uint32_t sb_ = sbase + (s) * STAGE_BYTES; \
    _Pragma("unroll") \
    for (int h2 = 0; h2 < 2; h2++) { \
        CP16(sb_ + dstoff[h2],              pA[h2] + (kof), szA[h2]); \
        CP16(sb_ + TILE_BYTES + dstoff[h2], pB[h2] + (kof), 16u); \
    } \
} while (0)

    // ---- compute setup
    int wm = (wid & 1) * 64, wn = (wid >> 1) * 32;
    uint32_t a_off = (uint32_t)((wm + (lane & 15)) * ROWB + (lane >> 4) * 16);
    uint32_t b_off = (uint32_t)((wn + (lane & 7) + ((lane >> 4) << 3)) * ROWB +
                                ((lane >> 3) & 1) * 16);

    float acc[4][4][4];
#pragma unroll
    for (int i = 0; i < 4; i++)
#pragma unroll
        for (int j = 0; j < 4; j++)
#pragma unroll
            for (int q = 0; q < 4; q++) acc[i][j][q] = 0.f;

    const int nk = Kdim / BK;
    LOAD_STAGE(0, 0);
    CP_COMMIT();

    for (int ks = 0; ks < nk; ks++) {
        int s = ks & 1;
        CP_WAIT0();          // only stage ks's group can be pending
        __syncthreads();     // everyone done computing stage s^1 (prev iter)

        if (ks + 1 < nk) {
            LOAD_STAGE(s ^ 1, (ks + 1) * BK);  // safe: issued after barrier
            CP_COMMIT();
        }

        uint32_t sb = sbase + s * STAGE_BYTES;
#pragma unroll
        for (int h = 0; h < 2; h++) {  // two k16 steps per BK=32
            uint32_t bh[4][2];
#pragma unroll
            for (int jp = 0; jp < 2; jp++) {
                uint32_t tmp[4];
                LDSM_X4(tmp, sb + TILE_BYTES + b_off + jp * (16 * ROWB) + h * 32);
                bh[jp * 2][0] = tmp[0]; bh[jp * 2][1] = tmp[1];
                bh[jp * 2 + 1][0] = tmp[2]; bh[jp * 2 + 1][1] = tmp[3];
            }
#pragma unroll
            for (int i = 0; i < 4; i++) {
                uint32_t ah[4];
                LDSM_X4(ah, sb + a_off + i * (16 * ROWB) + h * 32);
#pragma unroll
                for (int j = 0; j < 4; j++)
                    MMA_F16(acc[i][j], ah, bh[j]);
            }
        }
    }

    // ---- epilogue
    int rin = lane >> 2, cin = (lane & 3) * 2;
    if (MODE == 0) {
        // acc[i][jp*2] = gate, acc[i][jp*2+1] = up for the SAME logical cols
        int midcol0 = (n0 + wn) >> 1;  // logical mid col base for this warp
#pragma unroll
        for (int i = 0; i < 4; i++)
#pragma unroll
            for (int jp = 0; jp < 2; jp++) {
                const float* g = acc[i][jp * 2];
                const float* u = acc[i][jp * 2 + 1];
                int colb = midcol0 + jp * 8 + cin;
#pragma unroll
                for (int hf = 0; hf < 2; hf++) {
                    float m0 = silu_mul(g[hf * 2 + 0], u[hf * 2 + 0]);
                    float m1 = silu_mul(g[hf * 2 + 1], u[hf * 2 + 1]);
                    ushort2 h2v;
                    h2v.x = h16(m0); h2v.y = h16(m1);
                    size_t off = (size_t)(row0 + wm + i * 16 + rin + hf * 8) * I_DIM + colb;
                    *(ushort2*)(d_midh + off) = h2v;
                }
            }
    } else {
        // fused combine: out[token] += w_row * acc  (2 adds/element total)
        int   tokA[4], tokB[4];
        float wA[4], wB[4];
#pragma unroll
        for (int i = 0; i < 4; i++) {
            int rr = row0 + wm + i * 16 + rin;
            tokA[i] = d_tok[rr];     wA[i] = d_roww[rr];
            tokB[i] = d_tok[rr + 8]; wB[i] = d_roww[rr + 8];
        }
#pragma unroll
        for (int i = 0; i < 4; i++)
#pragma unroll
            for (int j = 0; j < 4; j++) {
                int col = n0 + wn + j * 8 + cin;
                if (tokA[i] >= 0) {
                    float* p = out + (size_t)tokA[i] * H_DIM + col;
                    atomicAdd(p,     wA[i] * acc[i][j][0]);
                    atomicAdd(p + 1, wA[i] * acc[i][j][1]);
                }
                if (tokB[i] >= 0) {
                    float* p = out + (size_t)tokB[i] * H_DIM + col;
                    atomicAdd(p,     wB[i] * acc[i][j][2]);
                    atomicAdd(p + 1, wB[i] * acc[i][j][3]);
                }
            }
    }
#undef LOAD_STAGE
}

// ---------------------------------------------------------------------------
extern "C" void kernel_launch(void* const* d_in, const int* in_sizes, int n_in,
                              void* d_out, int out_size) {
    const float* x  = (const float*)d_in[0];  // [4096, 1024]
    const float* gw = (const float*)d_in[1];  // [1024, 8]
    const float* Wg = (const float*)d_in[2];  // [8, 1024, 2048]
    const float* Wu = (const float*)d_in[3];  // [8, 1024, 2048]
    const float* Wd = (const float*)d_in[4];  // [8, 2048, 1024]
    float* out = (float*)d_out;               // final (4194304) then logits (32768)
    float* out_logits = out + (size_t)T_TOK * H_DIM;

    static cudaStream_t s_side = nullptr;
    static cudaEvent_t ev_fork = nullptr, ev_join = nullptr;
    if (!s_side) {
        cudaStreamCreateWithFlags(&s_side, cudaStreamNonBlocking);
        cudaEventCreateWithFlags(&ev_fork, cudaEventDisableTiming);
        cudaEventCreateWithFlags(&ev_join, cudaEventDisableTiming);
        cudaFuncSetAttribute(mma_gemm_kernel<0>, cudaFuncAttributeMaxDynamicSharedMemorySize, SMEM_TOTAL);
        cudaFuncSetAttribute(mma_gemm_kernel<1>, cudaFuncAttributeMaxDynamicSharedMemorySize, SMEM_TOTAL);
    }

    // Fork: weight transposes on a side stream, overlapped with dispatch chain
    cudaEventRecord(ev_fork, 0);
    cudaStreamWaitEvent(s_side, ev_fork, 0);
    wtrans_kernel<<<dim3(I_DIM / 32, H_DIM / 64, N_EXP), 256, 0, s_side>>>(Wg, 0);
    wtrans_kernel<<<dim3(I_DIM / 32, H_DIM / 64, N_EXP), 256, 0, s_side>>>(Wu, 1);
    wtrans_kernel<<<dim3(H_DIM / 32, I_DIM / 64, N_EXP), 256, 0, s_side>>>(Wd, 2);
    cudaEventRecord(ev_join, s_side);

    // Main stream: fused zero+convx+router, then scatter (with inline scan)
    pre_kernel<<<8704, 256>>>(x, gw, out, out_logits);
    scatter_kernel<<<17, 256>>>();

    cudaStreamWaitEvent(0, ev_join, 0);

    // GEMM1 (fused act) and GEMM2 (fused combine)
    mma_gemm_kernel<0><<<dim3(NROWT, (2 * I_DIM) / BN), 256, SMEM_TOTAL>>>(nullptr);
    mma_gemm_kernel<1><<<dim3(NROWT, H_DIM / BN), 256, SMEM_TOTAL>>>(out);

    // Reset dispatch state for the next (graph-replayed) call
    tail_kernel<<<1, 32>>>();
}